// round 8
// baseline (speedup 1.0000x reference)
#include <cuda_runtime.h>
#include <cuda_bf16.h>

#define NT 512
#define TOK 128

// Pre-swizzled [N][K] bf16 weight images (hi/lo split), 256B rows, XOR-16B swizzle.
// g_b1: w_qkv with HEAD-GROUPED column order: image row n' = h*48 + blk*16 + i
//       (blk 0=q,1=k,2=v) maps to original col blk*128 + h*16 + i.
__device__ __align__(16) unsigned char g_b1h[98304];
__device__ __align__(16) unsigned char g_b1l[98304];
__device__ __align__(16) unsigned char g_b2h[32768];   // w_proj [n][k]
__device__ __align__(16) unsigned char g_b2l[32768];

#define SWZ(r, b) ((unsigned)((r) * 256 + ((b) ^ (((r) & 7) << 4))))

// smem map (bytes)
#define OF_BQ   0u        // 1536
#define OF_BP   1536u     // 512
#define OF_SCR  2048u     // 16384: A2-frag exchange [wid16][slot8][lane32]
#define OF_AH   18432u    // 32768: x image hi
#define OF_AL   51200u    // 32768: x image lo
#define OF_B2H  83968u    // 32768
#define OF_B2L  116736u   // 32768
#define OF_B1H  149504u   // 24576: current round (2 heads, 96 rows)
#define OF_B1L  174080u   // 24576
#define SMEM_TOTAL 198656

__device__ __forceinline__ unsigned smem_u32(const void* p) {
    unsigned a;
    asm("{ .reg .u64 t; cvta.to.shared.u64 t, %1; cvt.u32.u64 %0, t; }" : "=r"(a) : "l"(p));
    return a;
}
__device__ __forceinline__ unsigned pk2(float a, float b) {
    __nv_bfloat162 t = __floats2bfloat162_rn(a, b);
    return *reinterpret_cast<unsigned*>(&t);
}
__device__ __forceinline__ float bfr(float v) {
    return __bfloat162float(__float2bfloat16_rn(v));
}
__device__ __forceinline__ void ldsm4(unsigned* r, unsigned addr) {
    asm volatile("ldmatrix.sync.aligned.m8n8.x4.shared.b16 {%0,%1,%2,%3}, [%4];"
                 : "=r"(r[0]), "=r"(r[1]), "=r"(r[2]), "=r"(r[3]) : "r"(addr));
}
__device__ __forceinline__ void mma16816(float* d, const unsigned* a, const unsigned* b) {
    asm volatile(
        "mma.sync.aligned.m16n8k16.row.col.f32.bf16.bf16.f32 "
        "{%0,%1,%2,%3}, {%4,%5,%6,%7}, {%8,%9}, {%0,%1,%2,%3};"
        : "+f"(d[0]), "+f"(d[1]), "+f"(d[2]), "+f"(d[3])
        : "r"(a[0]), "r"(a[1]), "r"(a[2]), "r"(a[3]), "r"(b[0]), "r"(b[1]));
}
__device__ __forceinline__ void cp16(unsigned dst, const void* src) {
    asm volatile("cp.async.cg.shared.global [%0], [%1], 16;" :: "r"(dst), "l"(src));
}
__device__ __forceinline__ float ex2f(float x) {
    float r; asm("ex2.approx.f32 %0, %1;" : "=f"(r) : "f"(x)); return r;
}
__device__ __forceinline__ float rcpf(float x) {
    float r; asm("rcp.approx.f32 %0, %1;" : "=f"(r) : "f"(x)); return r;
}

// ---------------- prep: fp32 weights -> swizzled bf16 hi/lo images ----------------
__global__ void prep_weights(const float* __restrict__ wq, const float* __restrict__ wp) {
    int i = blockIdx.x * blockDim.x + threadIdx.x;
    if (i < 6144) {                        // w_qkv: 384 head-grouped rows x 16 k-chunks
        int n = i >> 4, kc = i & 15, k0 = kc * 8;
        int h = n / 48, rem = n % 48, blk = rem >> 4, ii = rem & 15;
        int col = blk * 128 + h * 16 + ii; // original w_qkv column
        float hf[8], lf[8];
        #pragma unroll
        for (int j = 0; j < 8; j++) {
            float v = wq[(k0 + j) * 384 + col];
            hf[j] = bfr(v);
            lf[j] = v - hf[j];
        }
        unsigned off = SWZ(n, kc * 16);
        *(uint4*)(g_b1h + off) = make_uint4(pk2(hf[0], hf[1]), pk2(hf[2], hf[3]),
                                            pk2(hf[4], hf[5]), pk2(hf[6], hf[7]));
        *(uint4*)(g_b1l + off) = make_uint4(pk2(lf[0], lf[1]), pk2(lf[2], lf[3]),
                                            pk2(lf[4], lf[5]), pk2(lf[6], lf[7]));
    } else if (i < 8192) {                 // w_proj: 128 rows x 16 chunks
        int j2 = i - 6144;
        int n = j2 >> 4, kc = j2 & 15, k0 = kc * 8;
        float hf[8], lf[8];
        #pragma unroll
        for (int j = 0; j < 8; j++) {
            float v = wp[(k0 + j) * 128 + n];
            hf[j] = bfr(v);
            lf[j] = v - hf[j];
        }
        unsigned off = SWZ(n, kc * 16);
        *(uint4*)(g_b2h + off) = make_uint4(pk2(hf[0], hf[1]), pk2(hf[2], hf[3]),
                                            pk2(hf[4], hf[5]), pk2(hf[6], hf[7]));
        *(uint4*)(g_b2l + off) = make_uint4(pk2(lf[0], lf[1]), pk2(lf[2], lf[3]),
                                            pk2(lf[4], lf[5]), pk2(lf[6], lf[7]));
    }
}

// ---------------- main fused kernel: 16 warps, m16 tiles ----------------
__global__ void __launch_bounds__(NT, 1)
chan_attn_reg(const float* __restrict__ x, const float* __restrict__ bq,
              const float* __restrict__ bp, float* __restrict__ out)
{
    extern __shared__ __align__(16) unsigned char smem[];
    const unsigned sb = smem_u32(smem);
    const int tid = threadIdx.x, wid = tid >> 5, lane = tid & 31;
    const int wm = wid >> 1, wh = wid & 1, p = lane & 3;
    const long long tb = (long long)blockIdx.x * TOK;

    float* sBq = (float*)(smem + OF_BQ);
    float* sBp = (float*)(smem + OF_BP);
    if (tid < 384) sBq[tid] = bq[tid];
    if (tid < 128) sBp[tid] = bp[tid];

    // prologue cp.async: B2 (64KB) + B1 round0 (48KB)
    #pragma unroll
    for (int it = 0; it < 4; it++) {
        int i = tid + it * NT;
        cp16(sb + OF_B2H + i * 16, g_b2h + i * 16);
        cp16(sb + OF_B2L + i * 16, g_b2l + i * 16);
    }
    #pragma unroll
    for (int it = 0; it < 3; it++) {
        int i = tid + it * NT;
        cp16(sb + OF_B1H + i * 16, g_b1h + i * 16);
        cp16(sb + OF_B1L + i * 16, g_b1l + i * 16);
    }
    asm volatile("cp.async.commit_group;" ::: "memory");

    // build A image from x (hi/lo bf16, swizzled [m][k]) — overlaps cp.async drain
    {
        const float4* x4 = (const float4*)(x + tb * 128);
        #pragma unroll
        for (int it = 0; it < 8; it++) {
            int i = tid + it * NT;
            int m = i >> 5, c4 = i & 31;
            float4 v = x4[i];
            float h0 = bfr(v.x), h1 = bfr(v.y), h2 = bfr(v.z), h3 = bfr(v.w);
            unsigned off = SWZ(m, c4 * 8);
            *(uint2*)(smem + OF_AH + off) = make_uint2(pk2(h0, h1), pk2(h2, h3));
            *(uint2*)(smem + OF_AL + off) =
                make_uint2(pk2(v.x - h0, v.y - h1), pk2(v.z - h2, v.w - h3));
        }
    }

    const int a_r = (lane & 7) + ((lane >> 3) & 1) * 8;
    const int a_bs = (lane >> 4) * 16;
    const int b_r = (lane & 7) + (lane >> 4) * 8;
    const int b_bs = ((lane >> 3) & 1) * 16;

    float d2[8][4] = {};   // GEMM2 accumulator: m16 x n64, lives across rounds

    unsigned* scr = (unsigned*)(smem + OF_SCR);
    const int sbase = wid * 256 + lane;
    const int pbase = (wid ^ 1) * 256 + lane;

    #pragma unroll 1
    for (int r = 0; r < 4; r++) {
        asm volatile("cp.async.wait_group 0;" ::: "memory");
        __syncthreads();   // B1(round r) resident

        // ---- GEMM1: d1 = A1[m16] @ B1[head 2r+wh]  (m16 x n48, K=128) ----
        float d1[6][4] = {};
        #pragma unroll
        for (int kc = 0; kc < 8; kc++) {
            const int kb = kc * 32;
            unsigned ah[4], al[4], bh[3][4], bl[3][4];
            {
                unsigned off = SWZ(wm * 16 + a_r, kb + a_bs);
                ldsm4(ah, sb + OF_AH + off);
                ldsm4(al, sb + OF_AL + off);
            }
            #pragma unroll
            for (int g = 0; g < 3; g++) {
                unsigned off = SWZ(wh * 48 + g * 16 + b_r, kb + b_bs);
                ldsm4(bh[g], sb + OF_B1H + off);
                ldsm4(bl[g], sb + OF_B1L + off);
            }
            #pragma unroll
            for (int j = 0; j < 6; j++) {
                const unsigned* BH = bh[j >> 1] + (j & 1) * 2;
                const unsigned* BL = bl[j >> 1] + (j & 1) * 2;
                mma16816(d1[j], ah, BH);
                mma16816(d1[j], ah, BL);
                mma16816(d1[j], al, BH);
            }
        }
        __syncthreads();   // all warps done reading B1

        // refill B1 for next round (drains under softmax/GEMM2)
        if (r < 3) {
            const unsigned char* s1 = g_b1h + (r + 1) * 24576;
            const unsigned char* s2 = g_b1l + (r + 1) * 24576;
            #pragma unroll
            for (int it = 0; it < 3; it++) {
                int i = tid + it * NT;
                cp16(sb + OF_B1H + i * 16, s1 + i * 16);
                cp16(sb + OF_B1L + i * 16, s2 + i * 16);
            }
            asm volatile("cp.async.commit_group;" ::: "memory");
        }

        // ---- in-register softmax for head hh; output = GEMM2 A-fragments ----
        const int hh = 2 * r + wh;
        unsigned a2h[4], a2l[4];
        {
            const float scl2 = 0.0883883476483184405f * 1.4426950408889634f;
            const int c0 = 2 * p, c2 = 8 + 2 * p;
            float qb0 = sBq[hh * 16 + c0], qb1 = sBq[hh * 16 + c0 + 1];
            float qb2 = sBq[hh * 16 + c2], qb3 = sBq[hh * 16 + c2 + 1];
            float kb0 = sBq[128 + hh * 16 + c0], kb1 = sBq[128 + hh * 16 + c0 + 1];
            float kb2 = sBq[128 + hh * 16 + c2], kb3 = sBq[128 + hh * 16 + c2 + 1];
            float vb0 = sBq[256 + hh * 16 + c0], vb1 = sBq[256 + hh * 16 + c0 + 1];
            float vb2 = sBq[256 + hh * 16 + c2], vb3 = sBq[256 + hh * 16 + c2 + 1];

            float o[2][4];
            #pragma unroll
            for (int rh = 0; rh < 2; rh++) {
                float kk0 = d1[2][rh * 2 + 0] + kb0;
                float kk1 = d1[2][rh * 2 + 1] + kb1;
                float kk2 = d1[3][rh * 2 + 0] + kb2;
                float kk3 = d1[3][rh * 2 + 1] + kb3;
                float vv0 = d1[4][rh * 2 + 0] + vb0;
                float vv1 = d1[4][rh * 2 + 1] + vb1;
                float vv2 = d1[5][rh * 2 + 0] + vb2;
                float vv3 = d1[5][rh * 2 + 1] + vb3;
                float kf[16], vf[16];
                #pragma unroll
                for (int pp = 0; pp < 4; pp++) {
                    int sl = (lane & ~3) | pp;
                    kf[2 * pp]         = __shfl_sync(0xffffffffu, kk0, sl);
                    kf[2 * pp + 1]     = __shfl_sync(0xffffffffu, kk1, sl);
                    kf[8 + 2 * pp]     = __shfl_sync(0xffffffffu, kk2, sl);
                    kf[8 + 2 * pp + 1] = __shfl_sync(0xffffffffu, kk3, sl);
                    vf[2 * pp]         = __shfl_sync(0xffffffffu, vv0, sl);
                    vf[2 * pp + 1]     = __shfl_sync(0xffffffffu, vv1, sl);
                    vf[8 + 2 * pp]     = __shfl_sync(0xffffffffu, vv2, sl);
                    vf[8 + 2 * pp + 1] = __shfl_sync(0xffffffffu, vv3, sl);
                }
                float qv[4] = {qb0, qb1, qb2, qb3};
                #pragma unroll
                for (int i = 0; i < 4; i++) {
                    float ci = (d1[i >> 1][rh * 2 + (i & 1)] + qv[i]) * scl2;
                    float s = 0.f, a = 0.f;
                    #pragma unroll
                    for (int j = 0; j < 16; j++) {
                        float e = ex2f(ci * kf[j]);
                        s += e;
                        a = fmaf(e, vf[j], a);
                    }
                    o[rh][i] = a * rcpf(s);
                }
            }
            float h00 = bfr(o[0][0]), h01 = bfr(o[0][1]);
            float h10 = bfr(o[1][0]), h11 = bfr(o[1][1]);
            float h02 = bfr(o[0][2]), h03 = bfr(o[0][3]);
            float h12 = bfr(o[1][2]), h13 = bfr(o[1][3]);
            a2h[0] = pk2(h00, h01);  a2h[1] = pk2(h10, h11);
            a2h[2] = pk2(h02, h03);  a2h[3] = pk2(h12, h13);
            a2l[0] = pk2(o[0][0] - h00, o[0][1] - h01);
            a2l[1] = pk2(o[1][0] - h10, o[1][1] - h11);
            a2l[2] = pk2(o[0][2] - h02, o[0][3] - h03);
            a2l[3] = pk2(o[1][2] - h12, o[1][3] - h13);
        }

        // ---- exchange A2 fragments with pair warp (other head of round) ----
        #pragma unroll
        for (int e = 0; e < 4; e++) {
            scr[sbase + e * 32] = a2h[e];
            scr[sbase + (4 + e) * 32] = a2l[e];
        }
        asm volatile("bar.sync %0, %1;" :: "r"(1 + wm), "r"(64) : "memory");
        unsigned p2h[4], p2l[4];
        #pragma unroll
        for (int e = 0; e < 4; e++) {
            p2h[e] = scr[pbase + e * 32];
            p2l[e] = scr[pbase + (4 + e) * 32];
        }

        // ---- GEMM2 incremental accumulation: both heads of this round ----
        #pragma unroll
        for (int which = 0; which < 2; which++) {
            const unsigned* AH = which ? p2h : a2h;
            const unsigned* AL = which ? p2l : a2l;
            const int hd = 2 * r + (which ? (wh ^ 1) : wh);
            const int kb2 = hd * 32;
            unsigned b2h_[4][4], b2l_[4][4];
            #pragma unroll
            for (int g = 0; g < 4; g++) {
                unsigned off = SWZ(wh * 64 + g * 16 + b_r, kb2 + b_bs);
                ldsm4(b2h_[g], sb + OF_B2H + off);
                ldsm4(b2l_[g], sb + OF_B2L + off);
            }
            #pragma unroll
            for (int j = 0; j < 8; j++) {
                const unsigned* BH = b2h_[j >> 1] + (j & 1) * 2;
                const unsigned* BL = b2l_[j >> 1] + (j & 1) * 2;
                mma16816(d2[j], AH, BH);
                mma16816(d2[j], AH, BL);
                mma16816(d2[j], AL, BH);
            }
        }
        __syncthreads();   // scratch reads done before next round reuses it
    }

    // ---- epilogue: d2 + bias -> gmem ----
    {
        float* og = out + tb * 128;
        const int rl = wm * 16 + (lane >> 2);
        const int cb = wh * 64 + p * 2;
        #pragma unroll
        for (int j = 0; j < 8; j++) {
            int col = cb + j * 8;
            float b0 = sBp[col], b1 = sBp[col + 1];
            *(float2*)(og + rl * 128 + col) =
                make_float2(d2[j][0] + b0, d2[j][1] + b1);
            *(float2*)(og + (rl + 8) * 128 + col) =
                make_float2(d2[j][2] + b0, d2[j][3] + b1);
        }
    }
}

extern "C" void kernel_launch(void* const* d_in, const int* in_sizes, int n_in,
                              void* d_out, int out_size)
{
    const float *x = nullptr, *wq = nullptr, *bq = nullptr, *wp = nullptr, *bp = nullptr;
    long long xsz = 0;
    for (int i = 0; i < n_in; i++) {
        switch (in_sizes[i]) {
            case 49152: wq = (const float*)d_in[i]; break;
            case 384:   bq = (const float*)d_in[i]; break;
            case 16384: wp = (const float*)d_in[i]; break;
            case 128:   bp = (const float*)d_in[i]; break;
            default:    x  = (const float*)d_in[i]; xsz = in_sizes[i]; break;
        }
    }
    const int tokens = (int)(xsz / 128);

    prep_weights<<<32, 256>>>(wq, wp);

    cudaFuncSetAttribute(chan_attn_reg,
                         cudaFuncAttributeMaxDynamicSharedMemorySize, SMEM_TOTAL);
    chan_attn_reg<<<tokens / TOK, NT, SMEM_TOTAL>>>(x, bq, bp, (float*)d_out);
}

// round 10
// speedup vs baseline: 1.1768x; 1.1768x over previous
#include <cuda_runtime.h>
#include <cuda_bf16.h>

#define NT 256
#define TOK 64

// Pre-swizzled bf16 weight images (hi/lo split).
// g_b1: w_qkv, head-grouped rows (n' = h*48 + blk*16 + i -> col blk*128+h*16+i),
//       256B rows, XOR-16B swizzle (SWZ).
// g_b2: w_proj re-laid per ROUND: [round r][slot s][n:128][32B k-slice],
//       offset = r*8192 + s*4096 + n*32 + ((c ^ ((n>>2)&1))<<4), head = 2r+s,
//       chunk c covers k = hd*16 + c*8 .. +7.
__device__ __align__(16) unsigned char g_b1h[98304];
__device__ __align__(16) unsigned char g_b1l[98304];
__device__ __align__(16) unsigned char g_b2h[32768];
__device__ __align__(16) unsigned char g_b2l[32768];

#define SWZ(r, b) ((unsigned)((r) * 256 + ((b) ^ (((r) & 7) << 4))))

// smem map (bytes) — 108544 total => 2 CTAs/SM
#define OF_BQ    0u        // 1536
#define OF_BP    1536u     // 512
#define OF_SCR   2048u     // 8192: A2-frag exchange [wid8][slot8][lane32]
#define OF_AH    10240u    // 16384: x image hi (64 rows)
#define OF_AL    26624u    // 16384: x image lo
#define OF_B1H   43008u    // 24576: current round B1 hi (2 heads, 96 rows)
#define OF_B1L   67584u    // 24576
#define OF_B2RH  92160u    // 8192: current round B2 slice hi (2 slots x 4KB)
#define OF_B2RL  100352u   // 8192
#define SMEM_TOTAL 108544

__device__ __forceinline__ unsigned smem_u32(const void* p) {
    unsigned a;
    asm("{ .reg .u64 t; cvta.to.shared.u64 t, %1; cvt.u32.u64 %0, t; }" : "=r"(a) : "l"(p));
    return a;
}
__device__ __forceinline__ unsigned pk2(float a, float b) {
    __nv_bfloat162 t = __floats2bfloat162_rn(a, b);
    return *reinterpret_cast<unsigned*>(&t);
}
__device__ __forceinline__ float bfr(float v) {
    return __bfloat162float(__float2bfloat16_rn(v));
}
__device__ __forceinline__ void ldsm4(unsigned* r, unsigned addr) {
    asm volatile("ldmatrix.sync.aligned.m8n8.x4.shared.b16 {%0,%1,%2,%3}, [%4];"
                 : "=r"(r[0]), "=r"(r[1]), "=r"(r[2]), "=r"(r[3]) : "r"(addr));
}
__device__ __forceinline__ void mma16816(float* d, const unsigned* a, const unsigned* b) {
    asm volatile(
        "mma.sync.aligned.m16n8k16.row.col.f32.bf16.bf16.f32 "
        "{%0,%1,%2,%3}, {%4,%5,%6,%7}, {%8,%9}, {%0,%1,%2,%3};"
        : "+f"(d[0]), "+f"(d[1]), "+f"(d[2]), "+f"(d[3])
        : "r"(a[0]), "r"(a[1]), "r"(a[2]), "r"(a[3]), "r"(b[0]), "r"(b[1]));
}
__device__ __forceinline__ void cp16(unsigned dst, const void* src) {
    asm volatile("cp.async.cg.shared.global [%0], [%1], 16;" :: "r"(dst), "l"(src));
}
__device__ __forceinline__ float ex2f(float x) {
    float r; asm("ex2.approx.f32 %0, %1;" : "=f"(r) : "f"(x)); return r;
}
__device__ __forceinline__ float rcpf(float x) {
    float r; asm("rcp.approx.f32 %0, %1;" : "=f"(r) : "f"(x)); return r;
}

// ---------------- prep: fp32 weights -> swizzled bf16 hi/lo images ----------------
__global__ void prep_weights(const float* __restrict__ wq, const float* __restrict__ wp) {
    int i = blockIdx.x * blockDim.x + threadIdx.x;
    if (i < 6144) {                        // w_qkv: 384 head-grouped rows x 16 k-chunks
        int n = i >> 4, kc = i & 15, k0 = kc * 8;
        int h = n / 48, rem = n % 48, blk = rem >> 4, ii = rem & 15;
        int col = blk * 128 + h * 16 + ii;
        float hf[8], lf[8];
        #pragma unroll
        for (int j = 0; j < 8; j++) {
            float v = wq[(k0 + j) * 384 + col];
            hf[j] = bfr(v);
            lf[j] = v - hf[j];
        }
        unsigned off = SWZ(n, kc * 16);
        *(uint4*)(g_b1h + off) = make_uint4(pk2(hf[0], hf[1]), pk2(hf[2], hf[3]),
                                            pk2(hf[4], hf[5]), pk2(hf[6], hf[7]));
        *(uint4*)(g_b1l + off) = make_uint4(pk2(lf[0], lf[1]), pk2(lf[2], lf[3]),
                                            pk2(lf[4], lf[5]), pk2(lf[6], lf[7]));
    } else if (i < 8192) {                 // w_proj -> per-round slice layout
        int j2 = i - 6144;
        int n = j2 >> 4, kc = j2 & 15, k0 = kc * 8;
        int hd = kc >> 1, c = kc & 1, r = hd >> 1, s = hd & 1;
        float hf[8], lf[8];
        #pragma unroll
        for (int j = 0; j < 8; j++) {
            float v = wp[(k0 + j) * 128 + n];
            hf[j] = bfr(v);
            lf[j] = v - hf[j];
        }
        unsigned off = (unsigned)(r * 8192 + s * 4096 + n * 32 +
                                  ((c ^ ((n >> 2) & 1)) << 4));
        *(uint4*)(g_b2h + off) = make_uint4(pk2(hf[0], hf[1]), pk2(hf[2], hf[3]),
                                            pk2(hf[4], hf[5]), pk2(hf[6], hf[7]));
        *(uint4*)(g_b2l + off) = make_uint4(pk2(lf[0], lf[1]), pk2(lf[2], lf[3]),
                                            pk2(lf[4], lf[5]), pk2(lf[6], lf[7]));
    }
}

// ---------------- main fused kernel: 8 warps, 64 tokens, 2 CTAs/SM ----------------
__global__ void __launch_bounds__(NT, 2)
chan_attn_reg(const float* __restrict__ x, const float* __restrict__ bq,
              const float* __restrict__ bp, float* __restrict__ out)
{
    extern __shared__ __align__(16) unsigned char smem[];
    const unsigned sb = smem_u32(smem);
    const int tid = threadIdx.x, wid = tid >> 5, lane = tid & 31;
    const int wm = wid >> 1, wh = wid & 1, p = lane & 3;
    const long long tb = (long long)blockIdx.x * TOK;

    float* sBq = (float*)(smem + OF_BQ);
    float* sBp = (float*)(smem + OF_BP);
    for (int i = tid; i < 384; i += NT) sBq[i] = bq[i];
    if (tid < 128) sBp[tid] = bp[tid];

    // prologue cp.async: B1 round0 (24576B each of hi/lo => 6 iters) + B2 slice round0
    #pragma unroll
    for (int it = 0; it < 6; it++) {
        int i = tid + it * NT;
        cp16(sb + OF_B1H + i * 16, g_b1h + i * 16);
        cp16(sb + OF_B1L + i * 16, g_b1l + i * 16);
    }
    #pragma unroll
    for (int it = 0; it < 2; it++) {
        int i = tid + it * NT;
        cp16(sb + OF_B2RH + i * 16, g_b2h + i * 16);
        cp16(sb + OF_B2RL + i * 16, g_b2l + i * 16);
    }
    asm volatile("cp.async.commit_group;" ::: "memory");

    // build A image from x (64 rows, hi/lo bf16, swizzled [m][k])
    {
        const float4* x4 = (const float4*)(x + tb * 128);
        #pragma unroll
        for (int it = 0; it < 8; it++) {
            int i = tid + it * NT;
            int m = i >> 5, c4 = i & 31;
            float4 v = x4[i];
            float h0 = bfr(v.x), h1 = bfr(v.y), h2 = bfr(v.z), h3 = bfr(v.w);
            unsigned off = SWZ(m, c4 * 8);
            *(uint2*)(smem + OF_AH + off) = make_uint2(pk2(h0, h1), pk2(h2, h3));
            *(uint2*)(smem + OF_AL + off) =
                make_uint2(pk2(v.x - h0, v.y - h1), pk2(v.z - h2, v.w - h3));
        }
    }

    const int a_r = (lane & 7) + ((lane >> 3) & 1) * 8;
    const int a_bs = (lane >> 4) * 16;
    const int b_r = (lane & 7) + (lane >> 4) * 8;
    const int b_bs = ((lane >> 3) & 1) * 16;
    const int b2c = (lane >> 3) & 1;   // 16B chunk selector for B2 slices

    float d2[8][4] = {};   // GEMM2 accumulator: m16 x n64

    unsigned* scr = (unsigned*)(smem + OF_SCR);
    const int sbase = wid * 256 + lane;
    const int pbase = (wid ^ 1) * 256 + lane;

    #pragma unroll 1
    for (int r = 0; r < 4; r++) {
        asm volatile("cp.async.wait_group 0;" ::: "memory");
        __syncthreads();   // B1(r), B2 slice(r), (r==0: A image) resident

        // ---- GEMM1: d1 = A1[m16] @ B1[head 2r+wh]  (m16 x n48, K=128) ----
        float d1[6][4] = {};
        #pragma unroll
        for (int kc = 0; kc < 8; kc++) {
            const int kb = kc * 32;
            unsigned ah[4], al[4], bh[3][4], bl[3][4];
            {
                unsigned off = SWZ(wm * 16 + a_r, kb + a_bs);
                ldsm4(ah, sb + OF_AH + off);
                ldsm4(al, sb + OF_AL + off);
            }
            #pragma unroll
            for (int g = 0; g < 3; g++) {
                unsigned off = SWZ(wh * 48 + g * 16 + b_r, kb + b_bs);
                ldsm4(bh[g], sb + OF_B1H + off);
                ldsm4(bl[g], sb + OF_B1L + off);
            }
            #pragma unroll
            for (int j = 0; j < 6; j++) {
                const unsigned* BH = bh[j >> 1] + (j & 1) * 2;
                const unsigned* BL = bl[j >> 1] + (j & 1) * 2;
                mma16816(d1[j], ah, BH);
                mma16816(d1[j], ah, BL);
                mma16816(d1[j], al, BH);
            }
        }
        __syncthreads();   // all warps done reading B1

        // refill B1 for next round (drains under softmax/GEMM2)
        if (r < 3) {
            const unsigned char* s1 = g_b1h + (r + 1) * 24576;
            const unsigned char* s2 = g_b1l + (r + 1) * 24576;
            #pragma unroll
            for (int it = 0; it < 6; it++) {
                int i = tid + it * NT;
                cp16(sb + OF_B1H + i * 16, s1 + i * 16);
                cp16(sb + OF_B1L + i * 16, s2 + i * 16);
            }
            asm volatile("cp.async.commit_group;" ::: "memory");
        }

        // ---- in-register softmax for head hh ----
        const int hh = 2 * r + wh;
        unsigned a2h[4], a2l[4];
        {
            const float scl2 = 0.0883883476483184405f * 1.4426950408889634f;
            const int c0 = 2 * p, c2 = 8 + 2 * p;
            float qb0 = sBq[hh * 16 + c0], qb1 = sBq[hh * 16 + c0 + 1];
            float qb2 = sBq[hh * 16 + c2], qb3 = sBq[hh * 16 + c2 + 1];
            float kb0 = sBq[128 + hh * 16 + c0], kb1 = sBq[128 + hh * 16 + c0 + 1];
            float kb2 = sBq[128 + hh * 16 + c2], kb3 = sBq[128 + hh * 16 + c2 + 1];
            float vb0 = sBq[256 + hh * 16 + c0], vb1 = sBq[256 + hh * 16 + c0 + 1];
            float vb2 = sBq[256 + hh * 16 + c2], vb3 = sBq[256 + hh * 16 + c2 + 1];

            float o[2][4];
            #pragma unroll
            for (int rh = 0; rh < 2; rh++) {
                float kk0 = d1[2][rh * 2 + 0] + kb0;
                float kk1 = d1[2][rh * 2 + 1] + kb1;
                float kk2 = d1[3][rh * 2 + 0] + kb2;
                float kk3 = d1[3][rh * 2 + 1] + kb3;
                float vv0 = d1[4][rh * 2 + 0] + vb0;
                float vv1 = d1[4][rh * 2 + 1] + vb1;
                float vv2 = d1[5][rh * 2 + 0] + vb2;
                float vv3 = d1[5][rh * 2 + 1] + vb3;
                float kf[16], vf[16];
                #pragma unroll
                for (int pp = 0; pp < 4; pp++) {
                    int sl = (lane & ~3) | pp;
                    kf[2 * pp]         = __shfl_sync(0xffffffffu, kk0, sl);
                    kf[2 * pp + 1]     = __shfl_sync(0xffffffffu, kk1, sl);
                    kf[8 + 2 * pp]     = __shfl_sync(0xffffffffu, kk2, sl);
                    kf[8 + 2 * pp + 1] = __shfl_sync(0xffffffffu, kk3, sl);
                    vf[2 * pp]         = __shfl_sync(0xffffffffu, vv0, sl);
                    vf[2 * pp + 1]     = __shfl_sync(0xffffffffu, vv1, sl);
                    vf[8 + 2 * pp]     = __shfl_sync(0xffffffffu, vv2, sl);
                    vf[8 + 2 * pp + 1] = __shfl_sync(0xffffffffu, vv3, sl);
                }
                float qv[4] = {qb0, qb1, qb2, qb3};
                #pragma unroll
                for (int i = 0; i < 4; i++) {
                    float ci = (d1[i >> 1][rh * 2 + (i & 1)] + qv[i]) * scl2;
                    float s = 0.f, a = 0.f;
                    #pragma unroll
                    for (int j = 0; j < 16; j++) {
                        float e = ex2f(ci * kf[j]);
                        s += e;
                        a = fmaf(e, vf[j], a);
                    }
                    o[rh][i] = a * rcpf(s);
                }
            }
            float h00 = bfr(o[0][0]), h01 = bfr(o[0][1]);
            float h10 = bfr(o[1][0]), h11 = bfr(o[1][1]);
            float h02 = bfr(o[0][2]), h03 = bfr(o[0][3]);
            float h12 = bfr(o[1][2]), h13 = bfr(o[1][3]);
            a2h[0] = pk2(h00, h01);  a2h[1] = pk2(h10, h11);
            a2h[2] = pk2(h02, h03);  a2h[3] = pk2(h12, h13);
            a2l[0] = pk2(o[0][0] - h00, o[0][1] - h01);
            a2l[1] = pk2(o[1][0] - h10, o[1][1] - h11);
            a2l[2] = pk2(o[0][2] - h02, o[0][3] - h03);
            a2l[3] = pk2(o[1][2] - h12, o[1][3] - h13);
        }

        // ---- exchange A2 fragments with pair warp (other head of round) ----
        #pragma unroll
        for (int e = 0; e < 4; e++) {
            scr[sbase + e * 32] = a2h[e];
            scr[sbase + (4 + e) * 32] = a2l[e];
        }
        asm volatile("bar.sync %0, %1;" :: "r"(1 + wm), "r"(64) : "memory");
        unsigned p2h[4], p2l[4];
        #pragma unroll
        for (int e = 0; e < 4; e++) {
            p2h[e] = scr[pbase + e * 32];
            p2l[e] = scr[pbase + (4 + e) * 32];
        }

        // ---- GEMM2 incremental accumulation: both heads of this round ----
        #pragma unroll
        for (int which = 0; which < 2; which++) {
            const unsigned* AH = which ? p2h : a2h;
            const unsigned* AL = which ? p2l : a2l;
            const int s = which ? (wh ^ 1) : wh;   // slot within round slice
            unsigned b2h_[4][4], b2l_[4][4];
            #pragma unroll
            for (int g = 0; g < 4; g++) {
                int row = wh * 64 + g * 16 + b_r;
                unsigned off = (unsigned)(s * 4096 + row * 32 +
                                          ((b2c ^ ((row >> 2) & 1)) << 4));
                ldsm4(b2h_[g], sb + OF_B2RH + off);
                ldsm4(b2l_[g], sb + OF_B2RL + off);
            }
            #pragma unroll
            for (int j = 0; j < 8; j++) {
                const unsigned* BH = b2h_[j >> 1] + (j & 1) * 2;
                const unsigned* BL = b2l_[j >> 1] + (j & 1) * 2;
                mma16816(d2[j], AH, BH);
                mma16816(d2[j], AH, BL);
                mma16816(d2[j], AL, BH);
            }
        }
        __syncthreads();   // GEMM2 B2-slice reads + scratch reads done

        // refill B2 slice for next round (drains under next GEMM1)
        if (r < 3) {
            const unsigned char* s1 = g_b2h + (r + 1) * 8192;
            const unsigned char* s2 = g_b2l + (r + 1) * 8192;
            #pragma unroll
            for (int it = 0; it < 2; it++) {
                int i = tid + it * NT;
                cp16(sb + OF_B2RH + i * 16, s1 + i * 16);
                cp16(sb + OF_B2RL + i * 16, s2 + i * 16);
            }
            asm volatile("cp.async.commit_group;" ::: "memory");
        }
    }

    // ---- epilogue: d2 + bias -> gmem ----
    {
        float* og = out + tb * 128;
        const int rl = wm * 16 + (lane >> 2);
        const int cb = wh * 64 + p * 2;
        #pragma unroll
        for (int j = 0; j < 8; j++) {
            int col = cb + j * 8;
            float b0 = sBp[col], b1 = sBp[col + 1];
            *(float2*)(og + rl * 128 + col) =
                make_float2(d2[j][0] + b0, d2[j][1] + b1);
            *(float2*)(og + (rl + 8) * 128 + col) =
                make_float2(d2[j][2] + b0, d2[j][3] + b1);
        }
    }
}

extern "C" void kernel_launch(void* const* d_in, const int* in_sizes, int n_in,
                              void* d_out, int out_size)
{
    const float *x = nullptr, *wq = nullptr, *bq = nullptr, *wp = nullptr, *bp = nullptr;
    long long xsz = 0;
    for (int i = 0; i < n_in; i++) {
        switch (in_sizes[i]) {
            case 49152: wq = (const float*)d_in[i]; break;
            case 384:   bq = (const float*)d_in[i]; break;
            case 16384: wp = (const float*)d_in[i]; break;
            case 128:   bp = (const float*)d_in[i]; break;
            default:    x  = (const float*)d_in[i]; xsz = in_sizes[i]; break;
        }
    }
    const int tokens = (int)(xsz / 128);

    prep_weights<<<32, 256>>>(wq, wp);

    cudaFuncSetAttribute(chan_attn_reg,
                         cudaFuncAttributeMaxDynamicSharedMemorySize, SMEM_TOTAL);
    chan_attn_reg<<<tokens / TOK, NT, SMEM_TOTAL>>>(x, bq, bp, (float*)d_out);
}